// round 9
// baseline (speedup 1.0000x reference)
#include <cuda_runtime.h>

#define N_IMG 8
#define H 32
#define W 32
#define CIN 32
#define COUT 64
#define HO 30
#define WO 30
#define NPIX (N_IMG*HO*WO)       // 7200
#define PDIM (3*3*CIN)           // 288

typedef unsigned long long u64;
typedef unsigned int u32;

// Scratch (device globals: no allocation allowed in kernel_launch)
// g_vq: per element {vx,vx,vy,vy} pre-splatted for f32x2 (16B/element, 4MB)
__device__ __align__(16) float4 g_vq[N_IMG*H*W*CIN];
__device__ __align__(16) float  g_ek1[PDIM*COUT];     // exp(k1), [p][cout]
__device__ __align__(16) float  g_ek2[PDIM*COUT];     // exp(k2), [p][cout]

#define NV4 (N_IMG*H*W*CIN/4)    // 65536 float4 elements of x
#define VBLOCKS (NV4/256)        // 256
#define WBLOCKS ((PDIM*COUT + 255)/256)  // 72

// Two packed f32x2 multiplies, then fold BOTH products into each u32
// accumulator with one 3-input DPX max. Valid because every product is a
// strictly positive finite float (v >= 0.1, w = exp(k) > 0), and positive
// IEEE floats compare identically as unsigned ints.
__device__ __forceinline__ void mm3(u64 v0, u64 w0, u64 v1, u64 w1,
                                    u32& a0, u32& a1) {
    u32 p0lo, p0hi, p1lo, p1hi;
    asm("{\n\t"
        ".reg .b64 t0, t1;\n\t"
        "mul.rn.f32x2 t0, %4, %5;\n\t"
        "mul.rn.f32x2 t1, %6, %7;\n\t"
        "mov.b64 {%0, %1}, t0;\n\t"
        "mov.b64 {%2, %3}, t1;\n\t"
        "}"
        : "=r"(p0lo), "=r"(p0hi), "=r"(p1lo), "=r"(p1hi)
        : "l"(v0), "l"(w0), "l"(v1), "l"(w1));
    a0 = __vimax3_u32(a0, p0lo, p1lo);
    a1 = __vimax3_u32(a1, p0hi, p1hi);
}

// streaming (evict-first) 16B load: keeps the v stream out of the weights' L1
__device__ __forceinline__ ulonglong2 ldcs2(const ulonglong2* p) {
    ulonglong2 r;
    asm("ld.global.cs.v2.u64 {%0, %1}, [%2];" : "=l"(r.x), "=l"(r.y) : "l"(p));
    return r;
}

// ---------------------------------------------------------------------------
// Fused prep:
//   blocks [0,VBLOCKS):  per input float x -> float4 {vx,vx,vy,vy}
//   blocks [VBLOCKS, VBLOCKS+WBLOCKS): exp(weights)
// ---------------------------------------------------------------------------
__global__ void prep(const float* __restrict__ x,
                     const float* __restrict__ k1,
                     const float* __restrict__ k2) {
    const int b = blockIdx.x;
    if (b < VBLOCKS) {
        const int e4 = b*256 + threadIdx.x;          // float4 index into x
        const float4 xv = reinterpret_cast<const float4*>(x)[e4];
        float4* vp = g_vq + e4*4;
        const float a0 = fmaxf(xv.x, 0.1f), b0 = fmaxf(-xv.x, 0.1f);
        const float a1 = fmaxf(xv.y, 0.1f), b1 = fmaxf(-xv.y, 0.1f);
        const float a2 = fmaxf(xv.z, 0.1f), b2 = fmaxf(-xv.z, 0.1f);
        const float a3 = fmaxf(xv.w, 0.1f), b3 = fmaxf(-xv.w, 0.1f);
        vp[0] = make_float4(a0, a0, b0, b0);
        vp[1] = make_float4(a1, a1, b1, b1);
        vp[2] = make_float4(a2, a2, b2, b2);
        vp[3] = make_float4(a3, a3, b3, b3);
    } else {
        const int i = (b - VBLOCKS)*256 + threadIdx.x;
        if (i < PDIM*COUT) {
            g_ek1[i] = expf(k1[i]);
            g_ek2[i] = expf(k2[i]);
        }
    }
}

// ---------------------------------------------------------------------------
// Main: CTA = 64 threads = 2 warps (k-split 48/48), 2 pixels x 64 couts.
//   lane: cg = l&15 (4 couts), ps = l>>4 (pixel 0/1)
// Per 2-k warp-iter: 2 LDG.128.cs (v) + 4 LDG.128 (w) + 16 MUL.f32x2
//   + 16 VIMNMX3  -> 38 slots / 1024 products (vs 66 in R6).
// Warp 1 publishes partial maxes to smem; warp 0 combines + stores.
// ---------------------------------------------------------------------------
__global__ void __launch_bounds__(64, 16)
morph_main(const float* __restrict__ bias, float* __restrict__ out) {
    __shared__ uint4 s_red[32][4];

    const int t    = threadIdx.x;
    const int lane = t & 31;
    const int wrp  = t >> 5;      // 0 or 1: k-half
    const int cg   = lane & 15;   // cout group (4 couts)
    const int ps   = lane >> 4;   // pixel slot 0/1
    const int c0   = cg * 4;

    const int q  = blockIdx.x*2 + ps;   // flat pixel 0..7199
    const int n  = q / (HO*WO);
    const int r  = q - n*(HO*WO);
    const int ho = r / WO;
    const int wo = r - ho*WO;

    // v quads: (ho+i, wo+j, ci) -> vbase[(i*W+j)*CIN + ci], (j,ci) contiguous
    const ulonglong2* __restrict__ vbase =
        reinterpret_cast<const ulonglong2*>(g_vq) + ((n*H + ho)*W + wo)*CIN;
    // weight row = 64 floats = 16 ulonglong2; element cg of each row
    const ulonglong2* __restrict__ w1p = reinterpret_cast<const ulonglong2*>(g_ek1) + cg;
    const ulonglong2* __restrict__ w2p = reinterpret_cast<const ulonglong2*>(g_ek2) + cg;

    const int klo = wrp * 48;

    u32 m11[4], m12[4], m21[4], m22[4];
    #pragma unroll
    for (int k = 0; k < 4; k++) { m11[k]=0u; m12[k]=0u; m21[k]=0u; m22[k]=0u; }

    #pragma unroll 1
    for (int i = 0; i < 3; i++) {
        const ulonglong2* __restrict__ vp  = vbase + i*(W*CIN) + klo;
        const ulonglong2* __restrict__ aw1 = w1p + (i*96 + klo)*16;
        const ulonglong2* __restrict__ aw2 = w2p + (i*96 + klo)*16;

        #pragma unroll 4
        for (int k = 0; k < 48; k += 2) {
            const ulonglong2 va  = ldcs2(vp + k);        // {vxx, vyy} at k
            const ulonglong2 vb  = ldcs2(vp + k + 1);    // {vxx, vyy} at k+1
            const ulonglong2 w1a = __ldg(aw1 + k*16);
            const ulonglong2 w2a = __ldg(aw2 + k*16);
            const ulonglong2 w1b = __ldg(aw1 + (k+1)*16);
            const ulonglong2 w2b = __ldg(aw2 + (k+1)*16);
            mm3(va.x, w1a.x, vb.x, w1b.x, m11[0], m11[1]);
            mm3(va.x, w1a.y, vb.x, w1b.y, m11[2], m11[3]);
            mm3(va.x, w2a.x, vb.x, w2b.x, m12[0], m12[1]);
            mm3(va.x, w2a.y, vb.x, w2b.y, m12[2], m12[3]);
            mm3(va.y, w1a.x, vb.y, w1b.x, m21[0], m21[1]);
            mm3(va.y, w1a.y, vb.y, w1b.y, m21[2], m21[3]);
            mm3(va.y, w2a.x, vb.y, w2b.x, m22[0], m22[1]);
            mm3(va.y, w2a.y, vb.y, w2b.y, m22[2], m22[3]);
        }
    }

    // Cross-warp (k-half) max-combine: warp 1 publishes, warp 0 reduces+stores.
    if (wrp == 1) {
        s_red[lane][0] = make_uint4(m11[0], m11[1], m11[2], m11[3]);
        s_red[lane][1] = make_uint4(m12[0], m12[1], m12[2], m12[3]);
        s_red[lane][2] = make_uint4(m21[0], m21[1], m21[2], m21[3]);
        s_red[lane][3] = make_uint4(m22[0], m22[1], m22[2], m22[3]);
    }
    __syncthreads();
    if (wrp == 0) {
        const uint4 o11 = s_red[lane][0], o12 = s_red[lane][1];
        const uint4 o21 = s_red[lane][2], o22 = s_red[lane][3];
        m11[0] = umax(m11[0], o11.x); m11[1] = umax(m11[1], o11.y);
        m11[2] = umax(m11[2], o11.z); m11[3] = umax(m11[3], o11.w);
        m12[0] = umax(m12[0], o12.x); m12[1] = umax(m12[1], o12.y);
        m12[2] = umax(m12[2], o12.z); m12[3] = umax(m12[3], o12.w);
        m21[0] = umax(m21[0], o21.x); m21[1] = umax(m21[1], o21.y);
        m21[2] = umax(m21[2], o21.z); m21[3] = umax(m21[3], o21.w);
        m22[0] = umax(m22[0], o22.x); m22[1] = umax(m22[1], o22.y);
        m22[2] = umax(m22[2], o22.z); m22[3] = umax(m22[3], o22.w);

        const float4 bv = *reinterpret_cast<const float4*>(bias + c0);
        float4 res;
        res.x = __uint_as_float(m11[0]) - __uint_as_float(m12[0])
              - __uint_as_float(m21[0]) + __uint_as_float(m22[0]) + bv.x;
        res.y = __uint_as_float(m11[1]) - __uint_as_float(m12[1])
              - __uint_as_float(m21[1]) + __uint_as_float(m22[1]) + bv.y;
        res.z = __uint_as_float(m11[2]) - __uint_as_float(m12[2])
              - __uint_as_float(m21[2]) + __uint_as_float(m22[2]) + bv.z;
        res.w = __uint_as_float(m11[3]) - __uint_as_float(m12[3])
              - __uint_as_float(m21[3]) + __uint_as_float(m22[3]) + bv.w;

        *reinterpret_cast<float4*>(out + (size_t)q*COUT + c0) = res;
    }
}

// ---------------------------------------------------------------------------
extern "C" void kernel_launch(void* const* d_in, const int* in_sizes, int n_in,
                              void* d_out, int out_size) {
    const float* x    = (const float*)d_in[0];
    const float* k1   = (const float*)d_in[1];
    const float* k2   = (const float*)d_in[2];
    const float* bias = (const float*)d_in[3];
    float* out = (float*)d_out;

    prep<<<VBLOCKS + WBLOCKS, 256>>>(x, k1, k2);
    morph_main<<<NPIX/2, 64>>>(bias, out);
}

// round 10
// speedup vs baseline: 1.1374x; 1.1374x over previous
#include <cuda_runtime.h>

#define N_IMG 8
#define H 32
#define W 32
#define CIN 32
#define COUT 64
#define HO 30
#define WO 30
#define NPIX (N_IMG*HO*WO)       // 7200
#define PDIM (3*3*CIN)           // 288
#define HW (H*W)

typedef unsigned long long u64;
typedef unsigned int u32;

// Scratch (device globals: no allocation allowed in kernel_launch)
// g_vq: NCHW quad layout: [(n*CIN+ci)*H + h]*W + w  ->  {vx,vx,vy,vy} (16B)
// so 4 consecutive pixels (w..w+3) of one (ci,h) sit in 64B of ONE 128B line.
__device__ __align__(16) float4 g_vq[N_IMG*CIN*H*W];
__device__ __align__(16) float  g_ek1[PDIM*COUT];     // exp(k1), [p][cout]
__device__ __align__(16) float  g_ek2[PDIM*COUT];     // exp(k2), [p][cout]

#define TBLOCKS (N_IMG*H)                 // 256 transpose blocks
#define WBLOCKS ((PDIM*COUT + 1023)/1024) // 18 weight blocks

// Two packed f32x2 multiplies, fold both products into each u32 accumulator
// with one 3-input DPX max. Valid: all products are strictly positive finite
// floats (v >= 0.1, w = exp(k) > 0); positive IEEE floats order like u32.
__device__ __forceinline__ void mm3(u64 v0, u64 w0, u64 v1, u64 w1,
                                    u32& a0, u32& a1) {
    u32 p0lo, p0hi, p1lo, p1hi;
    asm("{\n\t"
        ".reg .b64 t0, t1;\n\t"
        "mul.rn.f32x2 t0, %4, %5;\n\t"
        "mul.rn.f32x2 t1, %6, %7;\n\t"
        "mov.b64 {%0, %1}, t0;\n\t"
        "mov.b64 {%2, %3}, t1;\n\t"
        "}"
        : "=r"(p0lo), "=r"(p0hi), "=r"(p1lo), "=r"(p1hi)
        : "l"(v0), "l"(w0), "l"(v1), "l"(w1));
    a0 = __vimax3_u32(a0, p0lo, p1lo);
    a1 = __vimax3_u32(a1, p0hi, p1hi);
}

// ---------------------------------------------------------------------------
// Fused prep:
//   blocks [0,TBLOCKS): clamp + NHWC -> NCHW-quad transpose via smem tile
//   blocks [TBLOCKS, TBLOCKS+WBLOCKS): exp(weights)
// ---------------------------------------------------------------------------
__global__ void prep(const float* __restrict__ x,
                     const float* __restrict__ k1,
                     const float* __restrict__ k2) {
    const int b = blockIdx.x;
    if (b < TBLOCKS) {
        __shared__ float tile[32][33];
        const int n = b >> 5;
        const int h = b & 31;
        {
            const int c = threadIdx.x;   // contiguous in gmem -> coalesced read
            const int w = threadIdx.y;
            tile[w][c] = x[(((n*H + h)*W + w)*CIN) + c];
        }
        __syncthreads();
        {
            const int w = threadIdx.x;   // contiguous in output -> coalesced write
            const int c = threadIdx.y;
            const float v  = tile[w][c];
            const float vp = fmaxf(v, 0.1f);
            const float vn = fmaxf(-v, 0.1f);
            g_vq[((n*CIN + c)*H + h)*W + w] = make_float4(vp, vp, vn, vn);
        }
    } else {
        const int i = (b - TBLOCKS)*1024 + threadIdx.y*32 + threadIdx.x;
        if (i < PDIM*COUT) {
            g_ek1[i] = expf(k1[i]);
            g_ek2[i] = expf(k2[i]);
        }
    }
}

// ---------------------------------------------------------------------------
// Main: ONE WARP per CTA = 4 pixels x 32 couts.
//   lane: cg = l&7 (4 couts), ps = l>>3 (pixel 0..3)
//   blockIdx: group = b>>1 (4 consecutive flat pixels), wh = b&1 (cout half)
// Per 2-ci iter: 2 v LDG.128 (4 consecutive quads -> ~1 wavefront each)
//   + 4 w LDG.128 (8 lanes x 16B = 128B = 1 wavefront each, broadcast x4)
//   + 16 MUL.f32x2 + 16 VIMNMX3.   ~6.6 wavefronts / 1024 products (vs 12).
// No smem, no sync: each lane owns its 4-cout x 4-table accumulators.
// ---------------------------------------------------------------------------
__global__ void __launch_bounds__(32)
morph_main(const float* __restrict__ bias, float* __restrict__ out) {
    const int lane  = threadIdx.x;
    const int cg    = lane & 7;    // cout group (4 couts)
    const int ps    = lane >> 3;   // pixel slot 0..3
    const int group = blockIdx.x >> 1;
    const int wh    = blockIdx.x & 1;
    const int c0    = wh*32 + cg*4;

    const int q  = group*4 + ps;        // flat pixel 0..7199
    const int n  = q / (HO*WO);
    const int r  = q - n*(HO*WO);
    const int ho = r / WO;
    const int wo = r - ho*WO;

    // NCHW quads: element (ci, ho+i, wo+j) at vbase + ci*HW + i*W + j
    const ulonglong2* __restrict__ vbase =
        reinterpret_cast<const ulonglong2*>(g_vq) + (n*CIN*H + ho)*W + wo;
    // weight row p = 16 quads; this lane's 4 couts at quad 16*p + wh*8 + cg
    const ulonglong2* __restrict__ w1base =
        reinterpret_cast<const ulonglong2*>(g_ek1) + wh*8 + cg;
    const ulonglong2* __restrict__ w2base =
        reinterpret_cast<const ulonglong2*>(g_ek2) + wh*8 + cg;

    u32 m11[4], m12[4], m21[4], m22[4];
    #pragma unroll
    for (int k = 0; k < 4; k++) { m11[k]=0u; m12[k]=0u; m21[k]=0u; m22[k]=0u; }

    #pragma unroll 1
    for (int ij = 0; ij < 9; ij++) {
        const int i = ij / 3;
        const int j = ij - 3*i;
        const ulonglong2* __restrict__ vp  = vbase + i*W + j;
        const ulonglong2* __restrict__ aw1 = w1base + (ij*CIN)*16;
        const ulonglong2* __restrict__ aw2 = w2base + (ij*CIN)*16;

        #pragma unroll 4
        for (int ci = 0; ci < CIN; ci += 2) {
            const ulonglong2 va  = __ldg(vp + ci*HW);       // {vxx, vyy}
            const ulonglong2 vb  = __ldg(vp + (ci+1)*HW);
            const ulonglong2 w1a = __ldg(aw1 + ci*16);
            const ulonglong2 w1b = __ldg(aw1 + (ci+1)*16);
            const ulonglong2 w2a = __ldg(aw2 + ci*16);
            const ulonglong2 w2b = __ldg(aw2 + (ci+1)*16);
            mm3(va.x, w1a.x, vb.x, w1b.x, m11[0], m11[1]);
            mm3(va.x, w1a.y, vb.x, w1b.y, m11[2], m11[3]);
            mm3(va.x, w2a.x, vb.x, w2b.x, m12[0], m12[1]);
            mm3(va.x, w2a.y, vb.x, w2b.y, m12[2], m12[3]);
            mm3(va.y, w1a.x, vb.y, w1b.x, m21[0], m21[1]);
            mm3(va.y, w1a.y, vb.y, w1b.y, m21[2], m21[3]);
            mm3(va.y, w2a.x, vb.y, w2b.x, m22[0], m22[1]);
            mm3(va.y, w2a.y, vb.y, w2b.y, m22[2], m22[3]);
        }
    }

    const float4 bv = *reinterpret_cast<const float4*>(bias + c0);
    float4 res;
    res.x = __uint_as_float(m11[0]) - __uint_as_float(m12[0])
          - __uint_as_float(m21[0]) + __uint_as_float(m22[0]) + bv.x;
    res.y = __uint_as_float(m11[1]) - __uint_as_float(m12[1])
          - __uint_as_float(m21[1]) + __uint_as_float(m22[1]) + bv.y;
    res.z = __uint_as_float(m11[2]) - __uint_as_float(m12[2])
          - __uint_as_float(m21[2]) + __uint_as_float(m22[2]) + bv.z;
    res.w = __uint_as_float(m11[3]) - __uint_as_float(m12[3])
          - __uint_as_float(m21[3]) + __uint_as_float(m22[3]) + bv.w;

    *reinterpret_cast<float4*>(out + (size_t)q*COUT + c0) = res;
}

// ---------------------------------------------------------------------------
extern "C" void kernel_launch(void* const* d_in, const int* in_sizes, int n_in,
                              void* d_out, int out_size) {
    const float* x    = (const float*)d_in[0];
    const float* k1   = (const float*)d_in[1];
    const float* k2   = (const float*)d_in[2];
    const float* bias = (const float*)d_in[3];
    float* out = (float*)d_out;

    prep<<<TBLOCKS + WBLOCKS, dim3(32,32)>>>(x, k1, k2);
    morph_main<<<(NPIX/4)*2, 32>>>(bias, out);
}